// round 11
// baseline (speedup 1.0000x reference)
#include <cuda_runtime.h>

// AdaptiveFilter: per-pixel learned bilateral filter.
// R4 geometry (16x16 tile, 128 threads, PY=2 vertical blocking) +
// GS-prescaled guidance (1-FFMA exp argument) +
// all 16 per-pixel logits preloaded & prescaled once (registers).
// out_c(p) = sum_k x_c(p+dk) * e_k / sum_k e_k,
//   e_k = 2^( w_k*log2e - (S*d_k)^2 ),  S = sqrt(50*log2e),
//   d_k = sum_c |g_c(p+dk)-g_c(p)|.   Softmax normalizer cancels.

namespace {
constexpr int B = 2, C = 3, H = 512, W = 512;
constexpr int BX = 16, BY = 8;       // 128 threads
constexpr int PY = 2;                // pixels per thread (vertical)
constexpr int TW = BX;               // 16
constexpr int TH = BY * PY;          // 16
constexpr int HALO = 3;
constexpr int SW = TW + 2 * HALO;    // 22
constexpr int SH = TH + 2 * HALO;    // 22
constexpr float LOG2E = 1.4426950408889634f;
constexpr float GS = 8.49321796f;    // sqrt(50*log2e)
}

__device__ __forceinline__ float ex2f(float v) {
    float r;
    asm("ex2.approx.f32 %0, %1;" : "=f"(r) : "f"(v));
    return r;
}

__global__ __launch_bounds__(BX * BY, 7)
void adaptive_filter_kernel(const float* __restrict__ x,
                            const float* __restrict__ g,
                            const float* __restrict__ w0,
                            float* __restrict__ out) {
    // Packed shared tiles: sgx = (S*g0, S*g1, S*g2, x0), sx2 = (x1, x2).
    __shared__ float4 sgx[SH][SW + 1];
    __shared__ float2 sx2[SH][SW + 1];

    const int b   = blockIdx.z;
    const int h0  = blockIdx.y * TH;
    const int w0c = blockIdx.x * TW;
    const int tid = threadIdx.y * BX + threadIdx.x;

    const float* __restrict__ gb = g + (size_t)b * C * H * W;
    const float* __restrict__ xb = x + (size_t)b * C * H * W;

    // Cooperative halo load with reflect padding (pad=3 << 512, one reflection).
    for (int idx = tid; idx < SH * SW; idx += BX * BY) {
        const int ty = idx / SW;
        const int tx = idx - ty * SW;
        int gy = h0 + ty - HALO;
        gy = gy < 0 ? -gy : (gy >= H ? 2 * H - 2 - gy : gy);
        int gx = w0c + tx - HALO;
        gx = gx < 0 ? -gx : (gx >= W ? 2 * W - 2 - gx : gx);
        const int p = gy * W + gx;
        sgx[ty][tx] = make_float4(gb[p] * GS, gb[H * W + p] * GS,
                                  gb[2 * H * W + p] * GS, xb[p]);
        sx2[ty][tx] = make_float2(xb[H * W + p], xb[2 * H * W + p]);
    }

    const int tx  = threadIdx.x;
    const int py0 = threadIdx.y * PY;       // tile-local row of pixel 0
    const int h   = h0 + py0;
    const int w   = w0c + tx;

    // Preload both pixels' 16 half-kernel logits once; prescale by log2 e.
    // (Overlaps with the halo fill before the barrier.)
    const float4* __restrict__ wb0 =
        reinterpret_cast<const float4*>(w0) + ((size_t)b * H * W + (size_t)h * W + w) * 4;
    const float4* __restrict__ wb1 = wb0 + (size_t)W * 4;

    float wl0[4][4], wl1[4][4];
#pragma unroll
    for (int r = 0; r < 4; ++r) {
        const float4 t0 = __ldg(&wb0[r]);
        wl0[r][0] = t0.x * LOG2E; wl0[r][1] = t0.y * LOG2E;
        wl0[r][2] = t0.z * LOG2E; wl0[r][3] = t0.w * LOG2E;
        const float4 t1 = __ldg(&wb1[r]);
        wl1[r][0] = t1.x * LOG2E; wl1[r][1] = t1.y * LOG2E;
        wl1[r][2] = t1.z * LOG2E; wl1[r][3] = t1.w * LOG2E;
    }

    __syncthreads();

    // Center guidance (pre-scaled) per pixel.
    const float4 cc0 = sgx[py0 + HALO][tx + HALO];
    const float4 cc1 = sgx[py0 + 1 + HALO][tx + HALO];

    float n0[PY] = {0.f, 0.f}, n1[PY] = {0.f, 0.f},
          n2[PY] = {0.f, 0.f}, dn[PY] = {0.f, 0.f};

#pragma unroll
    for (int i = 0; i < 8; ++i) {            // window rows py0+i
        const int row = py0 + i;
        const int hi0 = i < 4 ? i : 6 - i;           // pixel 0 logit row (i<=6)
        const int kr1 = i - 1;
        const int hi1 = kr1 < 4 ? kr1 : 6 - kr1;     // pixel 1 logit row (i>=1)

#pragma unroll
        for (int j = 0; j < 7; ++j) {
            const int hj = j < 4 ? j : 6 - j;
            // One shared read per (i,j) cell, consumed by both pixels.
            const float4 v = sgx[row][tx + j];
            const float2 u = sx2[row][tx + j];
            if (i <= 6) {
                const float s = fabsf(v.x - cc0.x) + fabsf(v.y - cc0.y) +
                                fabsf(v.z - cc0.z);
                const float e = ex2f(fmaf(s, -s, wl0[hi0][hj]));
                n0[0] = fmaf(v.w, e, n0[0]);
                n1[0] = fmaf(u.x, e, n1[0]);
                n2[0] = fmaf(u.y, e, n2[0]);
                dn[0] += e;
            }
            if (i >= 1) {
                const float s = fabsf(v.x - cc1.x) + fabsf(v.y - cc1.y) +
                                fabsf(v.z - cc1.z);
                const float e = ex2f(fmaf(s, -s, wl1[hi1][hj]));
                n0[1] = fmaf(v.w, e, n0[1]);
                n1[1] = fmaf(u.x, e, n1[1]);
                n2[1] = fmaf(u.y, e, n2[1]);
                dn[1] += e;
            }
        }
    }

    const float i0 = __fdividef(1.0f, dn[0]);
    const float i1 = __fdividef(1.0f, dn[1]);

    const size_t o = ((size_t)b * C * H + (size_t)h) * W + w;
    out[o]                         = n0[0] * i0;
    out[o + (size_t)H * W]         = n1[0] * i0;
    out[o + (size_t)2 * H * W]     = n2[0] * i0;
    out[o + W]                     = n0[1] * i1;
    out[o + W + (size_t)H * W]     = n1[1] * i1;
    out[o + W + (size_t)2 * H * W] = n2[1] * i1;
}

extern "C" void kernel_launch(void* const* d_in, const int* in_sizes, int n_in,
                              void* d_out, int out_size) {
    const float* x  = (const float*)d_in[0];
    const float* g  = (const float*)d_in[1];
    const float* w0 = (const float*)d_in[2];
    float* out = (float*)d_out;

    dim3 block(BX, BY);
    dim3 grid(W / TW, H / TH, B);
    adaptive_filter_kernel<<<grid, block>>>(x, g, w0, out);
}